// round 1
// baseline (speedup 1.0000x reference)
#include <cuda_runtime.h>
#include <stdint.h>

// Problem constants (shapes fixed by the reference):
//   seq:          (16, 4096, 1024) fp32
//   attn_weights: (16, 4096) fp32
//   out:          (16, 2049, 1024) fp32
#define BB 16
#define NN 4096
#define DD 1024
#define KK 2048           // kept tokens = N * (1 - 0.5)
#define D4 (DD / 4)       // 256 float4 per token row
#define CHUNKS 32         // token chunks for the pruned-sum tree reduction
#define TOK_PER_CHUNK (KK / CHUNKS)  // 64

// Scratch (no device allocation allowed in kernel_launch):
__device__ int   g_sorted[BB * NN];              // per-batch fully sorted token indices (desc by weight)
__device__ float g_partial[BB * CHUNKS * DD];    // partial sums of pruned tokens

// ---------------------------------------------------------------------------
// Kernel 1: per-batch full bitonic sort of (weight, index).
// Key = (~mono(float) << 32) | index  -> ascending u64 sort gives
// descending weight order with ties broken by ascending index,
// matching jax.lax.top_k semantics.
// ---------------------------------------------------------------------------
__global__ void topk_sort_kernel(const float* __restrict__ w) {
    __shared__ unsigned long long keys[NN];   // 32 KB
    const int b = blockIdx.x;
    const int tid = threadIdx.x;
    const float* row = w + b * NN;

    for (int i = tid; i < NN; i += blockDim.x) {
        unsigned int u = __float_as_uint(row[i]);
        // monotone mapping: order-preserving uint for float compare
        unsigned int mono = (u & 0x80000000u) ? ~u : (u | 0x80000000u);
        keys[i] = ((unsigned long long)(~mono) << 32) | (unsigned int)i;
    }
    __syncthreads();

    // Standard in-place bitonic sort, ascending.
    for (int k = 2; k <= NN; k <<= 1) {
        for (int j = k >> 1; j > 0; j >>= 1) {
            for (int i = tid; i < NN; i += blockDim.x) {
                int ixj = i ^ j;
                if (ixj > i) {
                    unsigned long long a = keys[i];
                    unsigned long long c = keys[ixj];
                    bool up = ((i & k) == 0);
                    if ((a > c) == up) { keys[i] = c; keys[ixj] = a; }
                }
            }
            __syncthreads();
        }
    }

    for (int i = tid; i < NN; i += blockDim.x)
        g_sorted[b * NN + i] = (int)(keys[i] & 0xFFFFFFFFu);
}

// ---------------------------------------------------------------------------
// Kernel 2: gather selected tokens. One CTA per (token j, batch b).
// 256 threads x float4 = 1024 floats (one full token row).
// ---------------------------------------------------------------------------
__global__ void gather_kernel(const float4* __restrict__ seq,
                              float4* __restrict__ out) {
    const int b = blockIdx.y;
    const int j = blockIdx.x;
    const int tok = g_sorted[b * NN + j];
    const float4* src = seq + ((size_t)b * NN + tok) * D4;
    float4* dst = out + ((size_t)b * (KK + 1) + j) * D4;
    dst[threadIdx.x] = src[threadIdx.x];
}

// ---------------------------------------------------------------------------
// Kernel 3: partial sums over pruned tokens.
// Grid (CHUNKS, BB); each CTA sums TOK_PER_CHUNK pruned token rows into a
// partial vector. Fixed summation order -> deterministic.
// ---------------------------------------------------------------------------
__global__ void partial_sum_kernel(const float4* __restrict__ seq) {
    const int b = blockIdx.y;
    const int c = blockIdx.x;
    const int tid = threadIdx.x;
    const int* idx = g_sorted + b * NN + KK + c * TOK_PER_CHUNK;

    float4 acc = make_float4(0.f, 0.f, 0.f, 0.f);
#pragma unroll 4
    for (int t = 0; t < TOK_PER_CHUNK; t++) {
        int tok = idx[t];
        float4 v = seq[((size_t)b * NN + tok) * D4 + tid];
        acc.x += v.x; acc.y += v.y; acc.z += v.z; acc.w += v.w;
    }
    float4* part = reinterpret_cast<float4*>(g_partial);
    part[((size_t)b * CHUNKS + c) * D4 + tid] = acc;
}

// ---------------------------------------------------------------------------
// Kernel 4: reduce partials and write the mix token (row KK of each batch).
// ---------------------------------------------------------------------------
__global__ void final_mix_kernel(float4* __restrict__ out) {
    const int b = blockIdx.x;
    const int tid = threadIdx.x;
    const float4* part = reinterpret_cast<const float4*>(g_partial);

    float4 acc = make_float4(0.f, 0.f, 0.f, 0.f);
#pragma unroll
    for (int c = 0; c < CHUNKS; c++) {
        float4 v = part[((size_t)b * CHUNKS + c) * D4 + tid];
        acc.x += v.x; acc.y += v.y; acc.z += v.z; acc.w += v.w;
    }
    // MIXUP_ALPHA * rem_sum / (rem_cnt + 1e-10), rem_cnt = 2048 exactly
    const float scale = 0.05f / (2048.0f + 1e-10f);
    acc.x *= scale; acc.y *= scale; acc.z *= scale; acc.w *= scale;
    out[((size_t)b * (KK + 1) + KK) * D4 + tid] = acc;
}

// ---------------------------------------------------------------------------
extern "C" void kernel_launch(void* const* d_in, const int* in_sizes, int n_in,
                              void* d_out, int out_size) {
    const float* seq = (const float*)d_in[0];          // (16, 4096, 1024)
    const float* attn_weights = (const float*)d_in[1]; // (16, 4096)
    float* out = (float*)d_out;                        // (16, 2049, 1024)

    (void)in_sizes; (void)n_in; (void)out_size;

    // 1) sort each batch's weights (16 CTAs, 1024 threads, 32 KB smem)
    topk_sort_kernel<<<BB, 1024>>>(attn_weights);

    // 2) gather selected tokens
    dim3 ggrid(KK, BB);
    gather_kernel<<<ggrid, 256>>>((const float4*)seq, (float4*)out);

    // 3) partial sums over pruned tokens
    dim3 pgrid(CHUNKS, BB);
    partial_sum_kernel<<<pgrid, 256>>>((const float4*)seq);

    // 4) final reduce + mix token
    final_mix_kernel<<<BB, 256>>>((float4*)out);
}

// round 2
// speedup vs baseline: 1.1221x; 1.1221x over previous
#include <cuda_runtime.h>
#include <stdint.h>

// Shapes (fixed): seq (16,4096,1024) f32, attn_weights (16,4096) f32,
// out (16,2049,1024) f32.
#define BB 16
#define NN 4096
#define DD 1024
#define KK 2048
#define D4 (DD / 4)
#define GROUP 32                      // token rows per CTA in fused kernel
#define NGROUPS (NN / GROUP)          // 128
#define SELGROUPS (KK / GROUP)        // 64
#define PCHUNKS (NGROUPS - SELGROUPS) // 64 pruned partial vectors per batch

__device__ int   g_sorted[BB * NN];
__device__ float g_partial[BB * PCHUNKS * DD];   // 4 MB scratch

// ---------------------------------------------------------------------------
// Kernel 1: per-batch bitonic full sort of (weight desc, index asc) keys.
// Compare-index formulation: exactly NN/2 compares per pass, no divergent
// skip iterations. Key = (~mono(f32) << 32) | idx so an ascending u64 sort
// matches jax.lax.top_k ordering (desc value, ties -> lower index).
// ---------------------------------------------------------------------------
__global__ __launch_bounds__(1024) void topk_sort_kernel(const float* __restrict__ w) {
    __shared__ unsigned long long keys[NN];     // 32 KB
    const int b = blockIdx.x;
    const int tid = threadIdx.x;
    const float* row = w + b * NN;

#pragma unroll
    for (int i = tid; i < NN; i += 1024) {
        unsigned int u = __float_as_uint(row[i]);
        unsigned int mono = (u & 0x80000000u) ? ~u : (u | 0x80000000u);
        keys[i] = ((unsigned long long)(~mono) << 32) | (unsigned int)i;
    }
    __syncthreads();

    for (int k = 2; k <= NN; k <<= 1) {
        for (int j = k >> 1; j > 0; j >>= 1) {
#pragma unroll
            for (int c = tid; c < NN / 2; c += 1024) {
                int i = ((c & ~(j - 1)) << 1) | (c & (j - 1));
                int p = i | j;
                bool up = ((i & k) == 0);
                unsigned long long a = keys[i];
                unsigned long long d = keys[p];
                if ((a > d) == up) { keys[i] = d; keys[p] = a; }
            }
            __syncthreads();
        }
    }

#pragma unroll
    for (int i = tid; i < NN; i += 1024)
        g_sorted[b * NN + i] = (int)(keys[i] & 0xFFFFFFFFu);
}

// ---------------------------------------------------------------------------
// Kernel 2 (fused): one pass over all 4096 sorted positions per batch.
// Positions [0,KK): copy row to output.  Positions [KK,NN): accumulate into
// a deterministic per-chunk partial sum. Every seq byte read exactly once.
// Grid (NGROUPS, BB), 256 threads (one float4 lane each).
// ---------------------------------------------------------------------------
__global__ __launch_bounds__(256) void gather_sum_kernel(const float4* __restrict__ seq,
                                                         float4* __restrict__ out) {
    const int b = blockIdx.y;
    const int g = blockIdx.x;
    const int tid = threadIdx.x;
    const int j0 = g * GROUP;

    __shared__ int toks[GROUP];
    if (tid < GROUP) toks[tid] = g_sorted[b * NN + j0 + tid];
    __syncthreads();

    const float4* sb = seq + (size_t)b * NN * D4;

    if (j0 < KK) {
        float4* dst = out + ((size_t)b * (KK + 1) + j0) * D4 + tid;
#pragma unroll 4
        for (int t = 0; t < GROUP; t++) {
            dst[(size_t)t * D4] = sb[(size_t)toks[t] * D4 + tid];
        }
    } else {
        float4 acc = make_float4(0.f, 0.f, 0.f, 0.f);
#pragma unroll 4
        for (int t = 0; t < GROUP; t++) {
            float4 v = sb[(size_t)toks[t] * D4 + tid];
            acc.x += v.x; acc.y += v.y; acc.z += v.z; acc.w += v.w;
        }
        float4* part = reinterpret_cast<float4*>(g_partial);
        part[((size_t)b * PCHUNKS + (g - SELGROUPS)) * D4 + tid] = acc;
    }
}

// ---------------------------------------------------------------------------
// Kernel 3: reduce PCHUNKS partials -> mix token (row KK). Grid BB x 1024
// threads, one scalar column per thread, coalesced.
// ---------------------------------------------------------------------------
__global__ __launch_bounds__(1024) void final_mix_kernel(float* __restrict__ out) {
    const int b = blockIdx.x;
    const int d = threadIdx.x;
    const float* part = g_partial + (size_t)b * PCHUNKS * DD + d;

    float acc = 0.f;
#pragma unroll 8
    for (int c = 0; c < PCHUNKS; c++)
        acc += part[(size_t)c * DD];

    const float scale = 0.05f / (2048.0f + 1e-10f);
    out[((size_t)b * (KK + 1) + KK) * DD + d] = acc * scale;
}

// ---------------------------------------------------------------------------
extern "C" void kernel_launch(void* const* d_in, const int* in_sizes, int n_in,
                              void* d_out, int out_size) {
    const float* seq = (const float*)d_in[0];
    const float* attn_weights = (const float*)d_in[1];
    float* out = (float*)d_out;
    (void)in_sizes; (void)n_in; (void)out_size;

    topk_sort_kernel<<<BB, 1024>>>(attn_weights);

    dim3 fgrid(NGROUPS, BB);
    gather_sum_kernel<<<fgrid, 256>>>((const float4*)seq, (float4*)out);

    final_mix_kernel<<<BB, 1024>>>(out);
}

// round 3
// speedup vs baseline: 1.2543x; 1.1179x over previous
#include <cuda_runtime.h>
#include <stdint.h>

// Shapes (fixed): seq (16,4096,1024) f32, attn_weights (16,4096) f32,
// out (16,2049,1024) f32.
#define BB 16
#define NN 4096
#define DD 1024
#define KK 2048
#define D4 (DD / 4)
#define GROUP 16                      // token rows per CTA in fused kernel
#define NGROUPS (NN / GROUP)          // 256
#define SELGROUPS (KK / GROUP)        // 128
#define PCHUNKS (NGROUPS - SELGROUPS) // 128 pruned partials per batch

__device__ int   g_sorted[BB * NN];
__device__ float g_partial[BB * PCHUNKS * DD];   // 8 MB scratch

// ---------------------------------------------------------------------------
// Bitonic helpers (64-bit keys: (~mono(f32) << 32) | idx, ascending sort
// == descending weight with ascending-index tie break == jax.lax.top_k).
// ---------------------------------------------------------------------------
__device__ __forceinline__ void cas(unsigned long long& a, unsigned long long& b, bool up) {
    if ((a > b) == up) { unsigned long long t = a; a = b; b = t; }
}

// Warp-shuffle compare-exchange stage: pair element i with i^j, j = 4*d.
__device__ __forceinline__ void shfl_stage(unsigned long long r[4], int d, bool up, int t) {
    const bool keepmin = (up == ((t & d) == 0));
#pragma unroll
    for (int p = 0; p < 4; p++) {
        unsigned long long o = __shfl_xor_sync(0xffffffffu, r[p], d);
        r[p] = keepmin ? (r[p] < o ? r[p] : o) : (r[p] > o ? r[p] : o);
    }
}

// All register-resident stages for bitonic step k: j = jmax..1 (jmax <= 64).
__device__ __forceinline__ void reg_stages(unsigned long long r[4], int t, int k, int jmax) {
    const bool up = (((4 * t) & k) == 0);   // valid for k >= 4
#pragma unroll
    for (int j = 64; j >= 4; j >>= 1)
        if (j <= jmax) shfl_stage(r, j >> 2, up, t);
    // j = 2 (intra-thread)
    cas(r[0], r[2], up); cas(r[1], r[3], up);
    // j = 1 (intra-thread)
    cas(r[0], r[1], up); cas(r[2], r[3], up);
}

// ---------------------------------------------------------------------------
// Kernel 1: per-batch full bitonic sort, hybrid register/shuffle/smem.
// Thread t owns elements 4t..4t+3. Only j>=128 stages touch smem.
// ---------------------------------------------------------------------------
__global__ __launch_bounds__(1024) void topk_sort_kernel(const float* __restrict__ w) {
    __shared__ unsigned long long sk[NN];   // 32 KB
    const int b = blockIdx.x;
    const int t = threadIdx.x;

    unsigned long long r[4];
#pragma unroll
    for (int p = 0; p < 4; p++) {
        int i = 4 * t + p;
        unsigned int u = __float_as_uint(w[b * NN + i]);
        unsigned int mono = (u & 0x80000000u) ? ~u : (u | 0x80000000u);
        r[p] = ((unsigned long long)(~mono) << 32) | (unsigned int)i;
    }

    // k = 2 (special per-position direction)
    cas(r[0], r[1], true);
    cas(r[2], r[3], false);
    // k = 4 .. 128: fully register-resident
    reg_stages(r, t, 4, 2);
    reg_stages(r, t, 8, 4);
    reg_stages(r, t, 16, 8);
    reg_stages(r, t, 32, 16);
    reg_stages(r, t, 64, 32);
    reg_stages(r, t, 128, 64);

    // k = 256 .. 4096: smem stages for j >= 128, then register tail
#pragma unroll
    for (int k = 256; k <= NN; k <<= 1) {
#pragma unroll
        for (int p = 0; p < 4; p++) sk[4 * t + p] = r[p];
        __syncthreads();
        for (int j = k >> 1; j >= 128; j >>= 1) {
#pragma unroll
            for (int cc = 0; cc < 2; cc++) {
                int c = t + cc * 1024;
                int i = ((c & ~(j - 1)) << 1) | (c & (j - 1));
                int p2 = i | j;
                bool up = ((i & k) == 0);
                unsigned long long a = sk[i];
                unsigned long long d = sk[p2];
                if ((a > d) == up) { sk[i] = d; sk[p2] = a; }
            }
            __syncthreads();
        }
#pragma unroll
        for (int p = 0; p < 4; p++) r[p] = sk[4 * t + p];
        reg_stages(r, t, k, 64);
    }

#pragma unroll
    for (int p = 0; p < 4; p++)
        g_sorted[b * NN + 4 * t + p] = (int)(r[p] & 0xFFFFFFFFu);
}

// ---------------------------------------------------------------------------
// Kernel 2 (fused): positions [0,KK) copy rows to out; [KK,NN) accumulate
// deterministic per-chunk partial sums. Every seq byte read exactly once.
// Grid (NGROUPS, BB), 256 threads (one float4 column lane each).
// ---------------------------------------------------------------------------
__global__ __launch_bounds__(256) void gather_sum_kernel(const float4* __restrict__ seq,
                                                         float4* __restrict__ out) {
    const int b = blockIdx.y;
    const int g = blockIdx.x;
    const int tid = threadIdx.x;
    const int j0 = g * GROUP;

    __shared__ int toks[GROUP];
    if (tid < GROUP) toks[tid] = g_sorted[b * NN + j0 + tid];
    __syncthreads();

    const float4* sb = seq + (size_t)b * NN * D4;

    if (j0 < KK) {
        float4* dst = out + ((size_t)b * (KK + 1) + j0) * D4 + tid;
#pragma unroll 4
        for (int t = 0; t < GROUP; t++)
            dst[(size_t)t * D4] = sb[(size_t)toks[t] * D4 + tid];
    } else {
        float4 acc = make_float4(0.f, 0.f, 0.f, 0.f);
#pragma unroll 4
        for (int t = 0; t < GROUP; t++) {
            float4 v = sb[(size_t)toks[t] * D4 + tid];
            acc.x += v.x; acc.y += v.y; acc.z += v.z; acc.w += v.w;
        }
        float4* part = reinterpret_cast<float4*>(g_partial);
        part[((size_t)b * PCHUNKS + (g - SELGROUPS)) * D4 + tid] = acc;
    }
}

// ---------------------------------------------------------------------------
// Kernel 3: reduce PCHUNKS partials -> mix token (row KK).
// Grid (4, BB): each CTA handles 256 columns of one batch.
// ---------------------------------------------------------------------------
__global__ __launch_bounds__(256) void final_mix_kernel(float* __restrict__ out) {
    const int b = blockIdx.y;
    const int d = blockIdx.x * 256 + threadIdx.x;
    const float* part = g_partial + (size_t)b * PCHUNKS * DD + d;

    float acc = 0.f;
#pragma unroll 8
    for (int c = 0; c < PCHUNKS; c++)
        acc += part[(size_t)c * DD];

    const float scale = 0.05f / (2048.0f + 1e-10f);
    out[((size_t)b * (KK + 1) + KK) * DD + d] = acc * scale;
}

// ---------------------------------------------------------------------------
extern "C" void kernel_launch(void* const* d_in, const int* in_sizes, int n_in,
                              void* d_out, int out_size) {
    const float* seq = (const float*)d_in[0];
    const float* attn_weights = (const float*)d_in[1];
    float* out = (float*)d_out;
    (void)in_sizes; (void)n_in; (void)out_size;

    topk_sort_kernel<<<BB, 1024>>>(attn_weights);

    dim3 fgrid(NGROUPS, BB);
    gather_sum_kernel<<<fgrid, 256>>>((const float4*)seq, (float4*)out);

    dim3 mgrid(4, BB);
    final_mix_kernel<<<mgrid, 256>>>(out);
}

// round 4
// speedup vs baseline: 1.3713x; 1.0933x over previous
#include <cuda_runtime.h>
#include <stdint.h>
#include <cub/block/block_radix_sort.cuh>

// Shapes (fixed): seq (16,4096,1024) f32, attn_weights (16,4096) f32,
// out (16,2049,1024) f32.
#define BB 16
#define NN 4096
#define DD 1024
#define KK 2048
#define D4 (DD / 4)
#define GROUP 16                      // token rows per CTA in fused kernel
#define NGROUPS (NN / GROUP)          // 256
#define SELGROUPS (KK / GROUP)        // 128
#define PCHUNKS (NGROUPS - SELGROUPS) // 128 pruned partials per batch

__device__ int   g_sorted[BB * NN];
__device__ float g_partial[BB * PCHUNKS * DD];   // 8 MB scratch

// ---------------------------------------------------------------------------
// Kernel 1: per-batch stable radix sort (CUB BlockRadixSort).
// Key = ~mono(f32): ascending radix sort == descending weight; stability
// gives ascending original index on ties == jax.lax.top_k ordering.
// ---------------------------------------------------------------------------
__global__ __launch_bounds__(1024) void topk_sort_kernel(const float* __restrict__ w) {
    typedef cub::BlockRadixSort<unsigned int, 1024, 4, int> Sorter;
    __shared__ typename Sorter::TempStorage temp;

    const int b = blockIdx.x;
    const int t = threadIdx.x;

    unsigned int keys[4];
    int vals[4];
#pragma unroll
    for (int p = 0; p < 4; p++) {
        int i = 4 * t + p;
        unsigned int u = __float_as_uint(w[b * NN + i]);
        unsigned int mono = (u & 0x80000000u) ? ~u : (u | 0x80000000u);
        keys[p] = ~mono;
        vals[p] = i;
    }

    Sorter(temp).Sort(keys, vals);   // stable, blocked arrangement

#pragma unroll
    for (int p = 0; p < 4; p++)
        g_sorted[b * NN + 4 * t + p] = vals[p];
}

// ---------------------------------------------------------------------------
// Kernel 2 (fused): positions [0,KK) copy rows to out; [KK,NN) accumulate
// deterministic per-chunk partial sums. Every seq byte read exactly once.
// Streaming loads/stores (data >> L2). Grid (NGROUPS, BB), 256 threads.
// ---------------------------------------------------------------------------
__global__ __launch_bounds__(256) void gather_sum_kernel(const float4* __restrict__ seq,
                                                         float4* __restrict__ out) {
    const int b = blockIdx.y;
    const int g = blockIdx.x;
    const int tid = threadIdx.x;
    const int j0 = g * GROUP;

    __shared__ int toks[GROUP];
    if (tid < GROUP) toks[tid] = g_sorted[b * NN + j0 + tid];
    __syncthreads();

    const float4* sb = seq + (size_t)b * NN * D4;

    if (j0 < KK) {
        float4* dst = out + ((size_t)b * (KK + 1) + j0) * D4 + tid;
        float4 v[GROUP];
#pragma unroll
        for (int t = 0; t < GROUP; t++)
            v[t] = __ldcs(sb + (size_t)toks[t] * D4 + tid);
#pragma unroll
        for (int t = 0; t < GROUP; t++)
            __stcs(dst + (size_t)t * D4, v[t]);
    } else {
        float4 acc = make_float4(0.f, 0.f, 0.f, 0.f);
#pragma unroll
        for (int t = 0; t < GROUP; t++) {
            float4 v = __ldcs(sb + (size_t)toks[t] * D4 + tid);
            acc.x += v.x; acc.y += v.y; acc.z += v.z; acc.w += v.w;
        }
        float4* part = reinterpret_cast<float4*>(g_partial);
        part[((size_t)b * PCHUNKS + (g - SELGROUPS)) * D4 + tid] = acc;
    }
}

// ---------------------------------------------------------------------------
// Kernel 3: reduce PCHUNKS partials -> mix token (row KK).
// Grid (4, BB): each CTA handles 256 columns of one batch.
// ---------------------------------------------------------------------------
__global__ __launch_bounds__(256) void final_mix_kernel(float* __restrict__ out) {
    const int b = blockIdx.y;
    const int d = blockIdx.x * 256 + threadIdx.x;
    const float* part = g_partial + (size_t)b * PCHUNKS * DD + d;

    float acc = 0.f;
#pragma unroll 8
    for (int c = 0; c < PCHUNKS; c++)
        acc += part[(size_t)c * DD];

    const float scale = 0.05f / (2048.0f + 1e-10f);
    out[((size_t)b * (KK + 1) + KK) * DD + d] = acc * scale;
}

// ---------------------------------------------------------------------------
extern "C" void kernel_launch(void* const* d_in, const int* in_sizes, int n_in,
                              void* d_out, int out_size) {
    const float* seq = (const float*)d_in[0];
    const float* attn_weights = (const float*)d_in[1];
    float* out = (float*)d_out;
    (void)in_sizes; (void)n_in; (void)out_size;

    topk_sort_kernel<<<BB, 1024>>>(attn_weights);

    dim3 fgrid(NGROUPS, BB);
    gather_sum_kernel<<<fgrid, 256>>>((const float4*)seq, (float4*)out);

    dim3 mgrid(4, BB);
    final_mix_kernel<<<mgrid, 256>>>(out);
}

// round 5
// speedup vs baseline: 1.4387x; 1.0491x over previous
#include <cuda_runtime.h>
#include <stdint.h>
#include <cub/block/block_radix_sort.cuh>

// Shapes (fixed): seq (16,4096,1024) f32, attn_weights (16,4096) f32,
// out (16,2049,1024) f32.
#define BB 16
#define NN 4096
#define DD 1024
#define KK 2048
#define D4 (DD / 4)
#define CHUNK 1024                    // elements per chunk-sort CTA
#define GROUP 16                      // token rows per CTA in fused kernel
#define NGROUPS (NN / GROUP)          // 256
#define SELGROUPS (KK / GROUP)        // 128
#define PCHUNKS (NGROUPS - SELGROUPS) // 128 pruned partials per batch

typedef unsigned long long u64;

__device__ u64   g_run[BB * NN];      // chunk-sorted composite keys
__device__ u64   g_run2[BB * NN];     // after pairwise merge (2048-runs)
__device__ int   g_sorted[BB * NN];
__device__ float g_partial[BB * PCHUNKS * DD];   // 8 MB scratch

// ---------------------------------------------------------------------------
// S1: sort 4 chunks of 1024 per batch. Grid (4, BB) = 64 CTAs.
// Key = ~mono(f32) (ascending u32 == descending weight); CUB stable sort
// preserves ascending index on ties. Output packed u64 = (key<<32)|idx so
// later merges compare a single integer (unique -> no tie ambiguity).
// ---------------------------------------------------------------------------
__global__ __launch_bounds__(256) void sort_chunks_kernel(const float* __restrict__ w) {
    typedef cub::BlockRadixSort<unsigned int, 256, 4, int> Sorter;
    __shared__ typename Sorter::TempStorage temp;

    const int b = blockIdx.y;
    const int c = blockIdx.x;
    const int t = threadIdx.x;

    unsigned int keys[4];
    int vals[4];
#pragma unroll
    for (int p = 0; p < 4; p++) {
        int i = c * CHUNK + 4 * t + p;
        unsigned int u = __float_as_uint(w[b * NN + i]);
        unsigned int mono = (u & 0x80000000u) ? ~u : (u | 0x80000000u);
        keys[p] = ~mono;
        vals[p] = i;
    }

    Sorter(temp).Sort(keys, vals);   // stable, blocked arrangement

#pragma unroll
    for (int p = 0; p < 4; p++)
        g_run[b * NN + c * CHUNK + 4 * t + p] =
            ((u64)keys[p] << 32) | (unsigned int)vals[p];
}

// ---------------------------------------------------------------------------
// S2: merge runs (0,1) and (2,3) -> two 2048-runs per batch.
// One thread per output element, merge-path binary search.
// ---------------------------------------------------------------------------
__global__ __launch_bounds__(256) void merge2_kernel() {
    const int b = blockIdx.y;
    const int k = blockIdx.x * 256 + threadIdx.x;   // 0..4095
    const int half = k >> 11;                        // which 2048-run
    const int kk = k & 2047;

    const u64* A = g_run + b * NN + half * 2048;
    const u64* B = A + 1024;

    int lo = kk > 1024 ? kk - 1024 : 0;
    int hi = kk < 1024 ? kk : 1024;
    while (lo < hi) {
        int mid = (lo + hi) >> 1;
        if (A[mid] <= B[kk - 1 - mid]) lo = mid + 1; else hi = mid;
    }
    int a = lo, bo = kk - lo;
    u64 av = (a  < 1024) ? A[a]  : ~0ull;
    u64 bv = (bo < 1024) ? B[bo] : ~0ull;
    g_run2[b * NN + half * 2048 + kk] = av < bv ? av : bv;
}

// ---------------------------------------------------------------------------
// S3: merge the two 2048-runs -> final sorted index array.
// ---------------------------------------------------------------------------
__global__ __launch_bounds__(256) void merge4_kernel() {
    const int b = blockIdx.y;
    const int k = blockIdx.x * 256 + threadIdx.x;   // 0..4095

    const u64* A = g_run2 + b * NN;
    const u64* B = A + 2048;

    int lo = k > 2048 ? k - 2048 : 0;
    int hi = k < 2048 ? k : 2048;
    while (lo < hi) {
        int mid = (lo + hi) >> 1;
        if (A[mid] <= B[k - 1 - mid]) lo = mid + 1; else hi = mid;
    }
    int a = lo, bo = k - lo;
    u64 av = (a  < 2048) ? A[a]  : ~0ull;
    u64 bv = (bo < 2048) ? B[bo] : ~0ull;
    u64 v = av < bv ? av : bv;
    g_sorted[b * NN + k] = (int)(v & 0xFFFFFFFFu);
}

// ---------------------------------------------------------------------------
// Fused gather/sum: positions [0,KK) copy rows to out; [KK,NN) accumulate
// deterministic per-chunk partial sums. Every seq byte read exactly once.
// Streaming loads/stores (data >> L2). Grid (NGROUPS, BB), 256 threads.
// ---------------------------------------------------------------------------
__global__ __launch_bounds__(256) void gather_sum_kernel(const float4* __restrict__ seq,
                                                         float4* __restrict__ out) {
    const int b = blockIdx.y;
    const int g = blockIdx.x;
    const int tid = threadIdx.x;
    const int j0 = g * GROUP;

    __shared__ int toks[GROUP];
    if (tid < GROUP) toks[tid] = g_sorted[b * NN + j0 + tid];
    __syncthreads();

    const float4* sb = seq + (size_t)b * NN * D4;

    if (j0 < KK) {
        float4* dst = out + ((size_t)b * (KK + 1) + j0) * D4 + tid;
        float4 v[GROUP];
#pragma unroll
        for (int t = 0; t < GROUP; t++)
            v[t] = __ldcs(sb + (size_t)toks[t] * D4 + tid);
#pragma unroll
        for (int t = 0; t < GROUP; t++)
            __stcs(dst + (size_t)t * D4, v[t]);
    } else {
        float4 acc = make_float4(0.f, 0.f, 0.f, 0.f);
#pragma unroll
        for (int t = 0; t < GROUP; t++) {
            float4 v = __ldcs(sb + (size_t)toks[t] * D4 + tid);
            acc.x += v.x; acc.y += v.y; acc.z += v.z; acc.w += v.w;
        }
        float4* part = reinterpret_cast<float4*>(g_partial);
        part[((size_t)b * PCHUNKS + (g - SELGROUPS)) * D4 + tid] = acc;
    }
}

// ---------------------------------------------------------------------------
// Reduce PCHUNKS partials -> mix token (row KK). Grid (4, BB).
// ---------------------------------------------------------------------------
__global__ __launch_bounds__(256) void final_mix_kernel(float* __restrict__ out) {
    const int b = blockIdx.y;
    const int d = blockIdx.x * 256 + threadIdx.x;
    const float* part = g_partial + (size_t)b * PCHUNKS * DD + d;

    float acc = 0.f;
#pragma unroll 8
    for (int c = 0; c < PCHUNKS; c++)
        acc += part[(size_t)c * DD];

    const float scale = 0.05f / (2048.0f + 1e-10f);
    out[((size_t)b * (KK + 1) + KK) * DD + d] = acc * scale;
}

// ---------------------------------------------------------------------------
extern "C" void kernel_launch(void* const* d_in, const int* in_sizes, int n_in,
                              void* d_out, int out_size) {
    const float* seq = (const float*)d_in[0];
    const float* attn_weights = (const float*)d_in[1];
    float* out = (float*)d_out;
    (void)in_sizes; (void)n_in; (void)out_size;

    dim3 sgrid(NN / CHUNK, BB);           // (4, 16)
    sort_chunks_kernel<<<sgrid, 256>>>(attn_weights);

    dim3 mgrid2(NN / 256, BB);            // (16, 16)
    merge2_kernel<<<mgrid2, 256>>>();
    merge4_kernel<<<mgrid2, 256>>>();

    dim3 fgrid(NGROUPS, BB);
    gather_sum_kernel<<<fgrid, 256>>>((const float4*)seq, (float4*)out);

    dim3 xgrid(4, BB);
    final_mix_kernel<<<xgrid, 256>>>(out);
}

// round 6
// speedup vs baseline: 1.4660x; 1.0190x over previous
#include <cuda_runtime.h>
#include <stdint.h>
#include <cub/block/block_radix_sort.cuh>

// Shapes (fixed): seq (16,4096,1024) f32, attn_weights (16,4096) f32,
// out (16,2049,1024) f32.
#define BB 16
#define NN 4096
#define DD 1024
#define KK 2048
#define D4 (DD / 4)
#define CHUNK 1024                    // elements per chunk-sort CTA
#define NRUNS (NN / CHUNK)            // 4 sorted runs per batch
#define GROUP 16                      // token rows per CTA in fused kernel
#define NGROUPS (NN / GROUP)          // 256
#define SELGROUPS (KK / GROUP)        // 128
#define PCHUNKS (NGROUPS - SELGROUPS) // 128 pruned partials per batch

typedef unsigned long long u64;

__device__ u64   g_run[BB * NN];      // chunk-sorted composite keys
__device__ int   g_sorted[BB * NN];
__device__ float g_partial[BB * PCHUNKS * DD];   // 8 MB scratch

// ---------------------------------------------------------------------------
// S1: sort 4 chunks of 1024 per batch. Grid (4, BB) = 64 CTAs.
// Key = ~mono(f32) (ascending u32 == descending weight); CUB stable sort
// preserves ascending index on ties. Output packed u64 = (key<<32)|idx so
// the rank kernel compares a single unique integer (no tie ambiguity);
// composite order == jax.lax.top_k order.
// ---------------------------------------------------------------------------
__global__ __launch_bounds__(256) void sort_chunks_kernel(const float* __restrict__ w) {
    typedef cub::BlockRadixSort<unsigned int, 256, 4, int> Sorter;
    __shared__ typename Sorter::TempStorage temp;

    const int b = blockIdx.y;
    const int c = blockIdx.x;
    const int t = threadIdx.x;

    unsigned int keys[4];
    int vals[4];
#pragma unroll
    for (int p = 0; p < 4; p++) {
        int i = c * CHUNK + 4 * t + p;
        unsigned int u = __float_as_uint(w[b * NN + i]);
        unsigned int mono = (u & 0x80000000u) ? ~u : (u | 0x80000000u);
        keys[p] = ~mono;
        vals[p] = i;
    }

    Sorter(temp).Sort(keys, vals);   // stable, blocked arrangement

#pragma unroll
    for (int p = 0; p < 4; p++)
        g_run[b * NN + c * CHUNK + 4 * t + p] =
            ((u64)keys[p] << 32) | (unsigned int)vals[p];
}

// ---------------------------------------------------------------------------
// S2: rank + scatter in one pass. Each thread owns one element of one run;
// final rank = local pos + sum over the other 3 runs of count(< key),
// computed with 3 interleaved branchless fixed-step binary searches
// (10 rounds, MLP=3). Then scatter the token index to its rank slot.
// ---------------------------------------------------------------------------
__global__ __launch_bounds__(256) void rank_scatter_kernel() {
    const int b = blockIdx.y;
    const int i = blockIdx.x * 256 + threadIdx.x;   // 0..4095
    const int r = i >> 10;                           // owning run
    const int p = i & (CHUNK - 1);                   // pos within run

    const u64* base = g_run + b * NN;
    const u64 key = base[i];

    const u64* A0 = base + (((r + 1) & 3) << 10);
    const u64* A1 = base + (((r + 2) & 3) << 10);
    const u64* A2 = base + (((r + 3) & 3) << 10);

    int c0 = 0, c1 = 0, c2 = 0;
#pragma unroll
    for (int step = CHUNK / 2; step > 0; step >>= 1) {
        u64 v0 = __ldg(A0 + c0 + step - 1);
        u64 v1 = __ldg(A1 + c1 + step - 1);
        u64 v2 = __ldg(A2 + c2 + step - 1);
        if (v0 < key) c0 += step;
        if (v1 < key) c1 += step;
        if (v2 < key) c2 += step;
    }

    const int rank = p + c0 + c1 + c2;
    g_sorted[b * NN + rank] = (int)(key & 0xFFFFFFFFu);
}

// ---------------------------------------------------------------------------
// Fused gather/sum: positions [0,KK) copy rows to out; [KK,NN) accumulate
// deterministic per-chunk partial sums. Every seq byte read exactly once.
// Streaming loads/stores (data >> L2). Copy path processes 2 batches of 8
// rows to keep register pressure (and thus occupancy) reasonable.
// Grid (NGROUPS, BB), 256 threads (one float4 column lane each).
// ---------------------------------------------------------------------------
__global__ __launch_bounds__(256) void gather_sum_kernel(const float4* __restrict__ seq,
                                                         float4* __restrict__ out) {
    const int b = blockIdx.y;
    const int g = blockIdx.x;
    const int tid = threadIdx.x;
    const int j0 = g * GROUP;

    __shared__ int toks[GROUP];
    if (tid < GROUP) toks[tid] = g_sorted[b * NN + j0 + tid];
    __syncthreads();

    const float4* sb = seq + (size_t)b * NN * D4;

    if (j0 < KK) {
        float4* dst = out + ((size_t)b * (KK + 1) + j0) * D4 + tid;
#pragma unroll
        for (int h = 0; h < 2; h++) {
            float4 v[8];
#pragma unroll
            for (int t = 0; t < 8; t++)
                v[t] = __ldcs(sb + (size_t)toks[h * 8 + t] * D4 + tid);
#pragma unroll
            for (int t = 0; t < 8; t++)
                __stcs(dst + (size_t)(h * 8 + t) * D4, v[t]);
        }
    } else {
        float4 acc = make_float4(0.f, 0.f, 0.f, 0.f);
#pragma unroll
        for (int t = 0; t < GROUP; t++) {
            float4 v = __ldcs(sb + (size_t)toks[t] * D4 + tid);
            acc.x += v.x; acc.y += v.y; acc.z += v.z; acc.w += v.w;
        }
        float4* part = reinterpret_cast<float4*>(g_partial);
        part[((size_t)b * PCHUNKS + (g - SELGROUPS)) * D4 + tid] = acc;
    }
}

// ---------------------------------------------------------------------------
// Reduce PCHUNKS partials -> mix token (row KK). Grid (4, BB).
// ---------------------------------------------------------------------------
__global__ __launch_bounds__(256) void final_mix_kernel(float* __restrict__ out) {
    const int b = blockIdx.y;
    const int d = blockIdx.x * 256 + threadIdx.x;
    const float* part = g_partial + (size_t)b * PCHUNKS * DD + d;

    float acc = 0.f;
#pragma unroll 8
    for (int c = 0; c < PCHUNKS; c++)
        acc += part[(size_t)c * DD];

    const float scale = 0.05f / (2048.0f + 1e-10f);
    out[((size_t)b * (KK + 1) + KK) * DD + d] = acc * scale;
}

// ---------------------------------------------------------------------------
extern "C" void kernel_launch(void* const* d_in, const int* in_sizes, int n_in,
                              void* d_out, int out_size) {
    const float* seq = (const float*)d_in[0];
    const float* attn_weights = (const float*)d_in[1];
    float* out = (float*)d_out;
    (void)in_sizes; (void)n_in; (void)out_size;

    dim3 sgrid(NRUNS, BB);                // (4, 16)
    sort_chunks_kernel<<<sgrid, 256>>>(attn_weights);

    dim3 rgrid(NN / 256, BB);             // (16, 16)
    rank_scatter_kernel<<<rgrid, 256>>>();

    dim3 fgrid(NGROUPS, BB);
    gather_sum_kernel<<<fgrid, 256>>>((const float4*)seq, (float4*)out);

    dim3 xgrid(4, BB);
    final_mix_kernel<<<xgrid, 256>>>(out);
}